// round 10
// baseline (speedup 1.0000x reference)
#include <cuda_runtime.h>
#include <cuda_bf16.h>

// Problem constants:
//   B = 128 rows, L = 262144 input cols
//   CROP_NUM = 26214, OUT_LEN = 235930
//   out[i, j] = audio[i, j]             for j <  starts[i]
//   out[i, j] = audio[i, j + CROP_NUM]  for j >= starts[i]
//
// Measured configuration matrix on sm_103a (kernel time):
//   ILP/thread:  2 -> 35.6us | 4 -> 35.1us | 8 -> 37.4us      => ILP=4
//   cache:  default 35.1 | __stcs 36.1 | evict_last+stcs 36.0 => default
// This file is the optimum of that sweep: ILP=4, quarter-stride,
// LDG.64 input loads, default STG.128 stores, 256 threads/block.

#define L_IN     262144u
#define CROP_NUM 26214u
#define OUT_LEN  235930u
#define TOTAL_OUT 30199040u              // 128 * 235930, divisible by 4
#define NVEC      (TOTAL_OUT / 4u)       // 7549760 float4 vectors
#define QVEC      (NVEC / 4u)            // 1887440 (NVEC divisible by 4)

__device__ __forceinline__ void process_vec(unsigned int t,
                                            const float* __restrict__ audio,
                                            const int*   __restrict__ starts,
                                            float*       __restrict__ out)
{
    unsigned int f0 = t * 4u;                    // flat output index
    unsigned int i  = f0 / OUT_LEN;              // row (IMAD.HI const-div)
    unsigned int j0 = f0 - i * OUT_LEN;          // col within row (always even)
    const float* __restrict__ rowp = audio + (size_t)i * L_IN;

    if (j0 + 3u < OUT_LEN) {
        const unsigned int start = (unsigned int)__ldg(&starts[i]);
        float4 v;
        if (j0 + 3u < start) {
            // Fully pre-crop: contiguous, 8B-aligned (j0 even) -> 2x LDG.64
            const float2* p = reinterpret_cast<const float2*>(rowp + j0);
            float2 a = __ldg(p);
            float2 b = __ldg(p + 1);
            v = make_float4(a.x, a.y, b.x, b.y);
        } else if (j0 >= start) {
            // Fully post-crop: contiguous shifted, j0+CROP even -> 2x LDG.64
            const float2* p = reinterpret_cast<const float2*>(rowp + j0 + CROP_NUM);
            float2 a = __ldg(p);
            float2 b = __ldg(p + 1);
            v = make_float4(a.x, a.y, b.x, b.y);
        } else {
            // Straddles the crop boundary (once per row): scalar selects
            unsigned int j;
            j = j0;      v.x = __ldg(&rowp[j + (j >= start ? CROP_NUM : 0u)]);
            j = j0 + 1u; v.y = __ldg(&rowp[j + (j >= start ? CROP_NUM : 0u)]);
            j = j0 + 2u; v.z = __ldg(&rowp[j + (j >= start ? CROP_NUM : 0u)]);
            j = j0 + 3u; v.w = __ldg(&rowp[j + (j >= start ? CROP_NUM : 0u)]);
        }
        reinterpret_cast<float4*>(out)[t] = v;
    } else {
        // Vector straddles a row boundary (<=127 total): fully scalar
        #pragma unroll
        for (int k = 0; k < 4; ++k) {
            unsigned int f  = f0 + (unsigned int)k;
            unsigned int ii = f / OUT_LEN;
            unsigned int jj = f - ii * OUT_LEN;
            unsigned int st = (unsigned int)__ldg(&starts[ii]);
            out[f] = __ldg(&audio[(size_t)ii * L_IN + jj + (jj >= st ? CROP_NUM : 0u)]);
        }
    }
}

__global__ __launch_bounds__(256)
void Crop_21345987461560_kernel(const float* __restrict__ audio,
                                const int*   __restrict__ starts,
                                float*       __restrict__ out)
{
    unsigned int t = blockIdx.x * blockDim.x + threadIdx.x;
    if (t < QVEC) {
        // 4 independent vectors per thread -> up to 8 LDG.64 + 4 STG.128
        // outstanding (measured optimum). Quarter-stride keeps each warp's
        // loads and stores fully coalesced.
        process_vec(t,             audio, starts, out);
        process_vec(t +     QVEC,  audio, starts, out);
        process_vec(t + 2u * QVEC, audio, starts, out);
        process_vec(t + 3u * QVEC, audio, starts, out);
    }
}

extern "C" void kernel_launch(void* const* d_in, const int* in_sizes, int n_in,
                              void* d_out, int out_size)
{
    const float* audio  = (const float*)d_in[0];   // [128, 262144] float32
    const int*   starts = (const int*)d_in[1];     // [128] int32
    float*       out    = (float*)d_out;           // [128, 235930] float32

    const unsigned int threads = 256;
    const unsigned int blocks  = (QVEC + threads - 1) / threads;  // 7373
    Crop_21345987461560_kernel<<<blocks, threads>>>(audio, starts, out);
}

// round 11
// speedup vs baseline: 1.0941x; 1.0941x over previous
#include <cuda_runtime.h>
#include <cuda_bf16.h>

// Problem constants:
//   B = 128 rows, L = 262144 input cols
//   CROP_NUM = 26214, OUT_LEN = 235930
//   out[i, j] = audio[i, j]             for j <  starts[i]
//   out[i, j] = audio[i, j + CROP_NUM]  for j >= starts[i]
//
// 2D-grid formulation: blockIdx.y = row, so `start` is block-uniform and
// there is no per-vector div/mod or row-straddle path. OUT_LEN % 4 == 2,
// so odd rows begin 8B-aligned: a 2-element prefix (pre = (row&1)*2)
// realigns to 16B, leaving exactly 58982 full float4 vectors per row plus
// 2 scalar leftover elements (prefix on odd rows, suffix on even rows).
//
// Measured on sm_103a: cache hints (__stcs / evict_last) consistently
// regress -> default loads/stores. ILP 4, 256 threads.

#define L_IN     262144u
#define CROP_NUM 26214u
#define OUT_LEN  235930u
#define ROW_VECS 58982u          // full aligned float4 vectors per row
#define BLK_VECS 1024u           // 256 threads * ILP 4
#define GRID_X   58u             // ceil(58982 / 1024)

__global__ __launch_bounds__(256)
void Crop_21345987461560_kernel(const float* __restrict__ audio,
                                const int*   __restrict__ starts,
                                float*       __restrict__ out)
{
    const unsigned int row = blockIdx.y;
    const unsigned int pre = (row & 1u) << 1;                 // 0 or 2
    const unsigned int start = (unsigned int)__ldg(&starts[row]);  // uniform
    const float* __restrict__ rowp = audio + (size_t)row * L_IN;

    // obase = row*OUT_LEN + pre is a multiple of 4 -> aligned float4 view.
    float4* __restrict__ out4 =
        reinterpret_cast<float4*>(out + (size_t)row * OUT_LEN + pre);

    const unsigned int v0 = blockIdx.x * BLK_VECS + threadIdx.x;

    #pragma unroll
    for (unsigned int k = 0; k < 4u; ++k) {
        unsigned int v = v0 + k * 256u;
        if (v < ROW_VECS) {
            unsigned int j0 = pre + v * 4u;                   // even
            float4 r;
            if (j0 >= start) {
                // Fully post-crop: contiguous shifted (8B-aligned) -> 2x LDG.64
                const float2* p = reinterpret_cast<const float2*>(rowp + j0 + CROP_NUM);
                float2 a = __ldg(p);
                float2 b = __ldg(p + 1);
                r = make_float4(a.x, a.y, b.x, b.y);
            } else if (j0 + 3u < start) {
                // Fully pre-crop: contiguous (8B-aligned) -> 2x LDG.64
                const float2* p = reinterpret_cast<const float2*>(rowp + j0);
                float2 a = __ldg(p);
                float2 b = __ldg(p + 1);
                r = make_float4(a.x, a.y, b.x, b.y);
            } else {
                // Straddles the crop boundary (one vector per row): scalar
                unsigned int j;
                j = j0;      r.x = __ldg(&rowp[j + (j >= start ? CROP_NUM : 0u)]);
                j = j0 + 1u; r.y = __ldg(&rowp[j + (j >= start ? CROP_NUM : 0u)]);
                j = j0 + 2u; r.z = __ldg(&rowp[j + (j >= start ? CROP_NUM : 0u)]);
                j = j0 + 3u; r.w = __ldg(&rowp[j + (j >= start ? CROP_NUM : 0u)]);
            }
            out4[v] = r;
        }
    }

    // 2 leftover scalar elements per row: prefix (j=0,1) on odd rows,
    // suffix (j=OUT_LEN-2, OUT_LEN-1) on even rows.
    if (blockIdx.x == 0 && threadIdx.x < 2u) {
        unsigned int j = (row & 1u) ? threadIdx.x
                                    : (OUT_LEN - 2u + threadIdx.x);
        out[(size_t)row * OUT_LEN + j] =
            __ldg(&rowp[j + (j >= start ? CROP_NUM : 0u)]);
    }
}

extern "C" void kernel_launch(void* const* d_in, const int* in_sizes, int n_in,
                              void* d_out, int out_size)
{
    const float* audio  = (const float*)d_in[0];   // [128, 262144] float32
    const int*   starts = (const int*)d_in[1];     // [128] int32
    float*       out    = (float*)d_out;           // [128, 235930] float32

    dim3 grid(GRID_X, 128u, 1u);                   // 58 x 128 = 7424 blocks
    Crop_21345987461560_kernel<<<grid, 256>>>(audio, starts, out);
}